// round 15
// baseline (speedup 1.0000x reference)
#include <cuda_runtime.h>
#include <cuda_fp16.h>
#include <cstdint>
#include <math.h>

#define B_     16
#define LQ     4096
#define LK     77
#define DMODEL 512
#define DCOND  768
#define NH     8
#define HD     64
#define INNER  512   // NH*HD
#define MKV    1232  // B_*LK
#define MKVP   1280  // padded to 128

// Scratch (allocation-free rule: __device__ globals; zero-initialized)
__device__ __half g_xh[(size_t)B_ * LQ * DMODEL];     // x fp16
__device__ __half g_ch[MKVP * DCOND];                 // cond fp16 (pad rows 0)
__device__ __half g_ah[(size_t)B_ * LQ * INNER];      // attention out fp16
__device__ __half g_qh[(size_t)B_ * LQ * INNER];      // Q*0.125 fp16 single
__device__ __half g_wqh[DMODEL * INNER];              // w_q single fp16
__device__ __half g_woh[DMODEL * INNER];              // w_o single fp16
__device__ __half g_wkvh[2 * INNER * DCOND];          // [w_k ; w_v] single fp16
__device__ __half g_kvh[(size_t)MKVP * 1024];         // K cols 0..511, V 512..1023

// ===========================================================================
// Helpers (base PTX only)
// ===========================================================================
__device__ __forceinline__ uint32_t smem_u32(const void* p) {
    uint32_t a;
    asm("{ .reg .u64 t; cvta.to.shared.u64 t, %1; cvt.u32.u64 %0, t; }" : "=r"(a) : "l"(p));
    return a;
}
__device__ __forceinline__ uint32_t swz128(uint32_t off) { return off ^ ((off >> 3) & 0x70); }

__device__ __forceinline__ void ldmatrix_x4(uint32_t* r, uint32_t addr) {
    asm volatile("ldmatrix.sync.aligned.m8n8.x4.shared.b16 {%0,%1,%2,%3}, [%4];"
        : "=r"(r[0]), "=r"(r[1]), "=r"(r[2]), "=r"(r[3]) : "r"(addr));
}
__device__ __forceinline__ void ldmatrix_x2(uint32_t* r, uint32_t addr) {
    asm volatile("ldmatrix.sync.aligned.m8n8.x2.shared.b16 {%0,%1}, [%2];"
        : "=r"(r[0]), "=r"(r[1]) : "r"(addr));
}
// fp16 MMA, fp32 accum
__device__ __forceinline__ void mma16816h(float* d, const uint32_t* a, const uint32_t* b) {
    asm volatile("mma.sync.aligned.m16n8k16.row.col.f32.f16.f16.f32 "
        "{%0,%1,%2,%3}, {%4,%5,%6,%7}, {%8,%9}, {%0,%1,%2,%3};"
        : "+f"(d[0]), "+f"(d[1]), "+f"(d[2]), "+f"(d[3])
        : "r"(a[0]), "r"(a[1]), "r"(a[2]), "r"(a[3]), "r"(b[0]), "r"(b[1]));
}
__device__ __forceinline__ void cp_async16(uint32_t dst, const void* src) {
    asm volatile("cp.async.cg.shared.global [%0], [%1], 16;" :: "r"(dst), "l"(src));
}
#define CP_COMMIT() asm volatile("cp.async.commit_group;" ::: "memory")
#define CP_WAIT3()  asm volatile("cp.async.wait_group 3;" ::: "memory")
#define CP_WAIT0()  asm volatile("cp.async.wait_group 0;" ::: "memory")

__device__ __forceinline__ uint32_t pack_h2(float x, float y) {
    __half2 h = __floats2half2_rn(x, y);
    return *(const uint32_t*)&h;
}

// fp32 -> single fp16
__global__ void cvt_h(const float4* __restrict__ in, uint2* __restrict__ out, int n4)
{
    const int i = blockIdx.x * blockDim.x + threadIdx.x;
    if (i >= n4) return;
    const float4 v = in[i];
    out[i] = make_uint2(pack_h2(v.x, v.y), pack_h2(v.z, v.w));
}

// ===========================================================================
// Narrow-tile fp16 GEMM (single B): 128x64 tile, K-chunk 64, 4-stage cp.async,
// 256 thr (8 warps, 4m x 2n), warp tile 32x32. 24KB/stage -> 2 CTA/SM.
// OUT: 0 = fp32 C; 1 = fp16 single (premul).
// ===========================================================================
#define SM_N (4 * 24576)

template <int KDIM, int LDC, int OUT>
__global__ void __launch_bounds__(256, 2)
gemm_n(const __half* __restrict__ A, const __half* __restrict__ Bw,
       float* __restrict__ C, __half* __restrict__ Oh, float premul)
{
    constexpr int NCHUNK = KDIM / 64;
    extern __shared__ char sm[];
    const uint32_t base = smem_u32(sm);
    const int tid  = threadIdx.x;
    const int wid  = tid >> 5;
    const int lane = tid & 31;
    const int wm   = wid & 3;
    const int wn   = wid >> 2;

    const int m0 = blockIdx.x * 128;
    const int n0 = blockIdx.y * 64;
    const __half* A0 = A  + (size_t)m0 * KDIM;
    const __half* B0 = Bw + (size_t)n0 * KDIM;

    float acc[2][4][4];
#pragma unroll
    for (int mt = 0; mt < 2; ++mt)
#pragma unroll
        for (int nt = 0; nt < 4; ++nt)
#pragma unroll
            for (int q = 0; q < 4; ++q) acc[mt][nt][q] = 0.f;

    uint32_t aRow0[2], bRow0[4];
#pragma unroll
    for (int mt = 0; mt < 2; ++mt)
        aRow0[mt] = (uint32_t)((wm * 32 + mt * 16 + (lane & 15)) * 128 + (lane >> 4) * 16);
#pragma unroll
    for (int nt = 0; nt < 4; ++nt)
        bRow0[nt] = (uint32_t)((wn * 32 + nt * 8 + (lane & 7)) * 128 + ((lane >> 3) & 1) * 16);

    auto issue_chunk = [&](int c, int buf) {
        const int kc = c * 64;
        const uint32_t tb = base + buf * 24576;
#pragma unroll
        for (int i = 0; i < 4; ++i) {
            const int idx = i * 256 + tid;
            const int row = idx >> 3, c8 = idx & 7;
            cp_async16(tb + swz128((uint32_t)(row * 128 + c8 * 16)),
                       A0 + (size_t)row * KDIM + kc + c8 * 8);
        }
#pragma unroll
        for (int i = 0; i < 2; ++i) {
            const int idx = i * 256 + tid;
            const int row = idx >> 3, c8 = idx & 7;
            cp_async16(tb + 16384 + swz128((uint32_t)(row * 128 + c8 * 16)),
                       B0 + (size_t)row * KDIM + kc + c8 * 8);
        }
    };

    issue_chunk(0, 0); CP_COMMIT();
    issue_chunk(1, 1); CP_COMMIT();
    issue_chunk(2, 2); CP_COMMIT();
    issue_chunk(3, 3); CP_COMMIT();

    for (int c = 0; c < NCHUNK; ++c) {
        const int buf = c & 3;
        CP_WAIT3();
        __syncthreads();

        const uint32_t bufA = base + buf * 24576;
        const uint32_t bufB = bufA + 16384;
#pragma unroll
        for (int kb = 0; kb < 4; ++kb) {
            const uint32_t kbyte = kb * 32;
            uint32_t Af[2][4], Bf[4][2];
#pragma unroll
            for (int mt = 0; mt < 2; ++mt) {
                const uint32_t off = aRow0[mt] + kbyte;
                ldmatrix_x4(Af[mt], bufA + (off ^ ((off >> 3) & 0x70)));
            }
#pragma unroll
            for (int nt = 0; nt < 4; ++nt) {
                const uint32_t off = bRow0[nt] + kbyte;
                ldmatrix_x2(Bf[nt], bufB + (off ^ ((off >> 3) & 0x70)));
            }
#pragma unroll
            for (int mt = 0; mt < 2; ++mt)
#pragma unroll
                for (int nt = 0; nt < 4; ++nt)
                    mma16816h(acc[mt][nt], Af[mt], Bf[nt]);
        }
        __syncthreads();
        if (c + 4 < NCHUNK) issue_chunk(c + 4, buf);
        CP_COMMIT();
    }

#pragma unroll
    for (int mt = 0; mt < 2; ++mt) {
        const int r = m0 + wm * 32 + mt * 16 + (lane >> 2);
#pragma unroll
        for (int nt = 0; nt < 4; ++nt) {
            const int cc = n0 + wn * 32 + nt * 8 + (lane & 3) * 2;
            if (OUT == 0) {
                *(float2*)(C + (size_t)r * LDC + cc)       = make_float2(acc[mt][nt][0], acc[mt][nt][1]);
                *(float2*)(C + (size_t)(r + 8) * LDC + cc) = make_float2(acc[mt][nt][2], acc[mt][nt][3]);
            } else {
                *(uint32_t*)(Oh + (size_t)r * LDC + cc)       = pack_h2(acc[mt][nt][0] * premul, acc[mt][nt][1] * premul);
                *(uint32_t*)(Oh + (size_t)(r + 8) * LDC + cc) = pack_h2(acc[mt][nt][2] * premul, acc[mt][nt][3] * premul);
            }
        }
    }
}

// ===========================================================================
// FA2-style fp16 HMMA attention: Q, K, V all single fp16 (80 MMAs/warp).
// grid (LQ/128, B_*NH), 256 threads, ~37KB smem -> 2 CTA/SM.
// ===========================================================================
#define AQ  0
#define AK  16384
#define AV  26624              // K: 80 rows x 128B = 10240
#define VT_B 176               // V^T: 64 rows x 176B = 11264
#define AT_SMEM (26624 + 64 * VT_B)   // 37888

__global__ __launch_bounds__(256, 2)
void attn_mma(const __half* __restrict__ Q, const __half* __restrict__ KV,
              __half* __restrict__ Oa)
{
    extern __shared__ char sm[];
    const uint32_t base = smem_u32(sm);
    const int tid  = threadIdx.x;
    const int w    = tid >> 5;
    const int lane = tid & 31;
    const int bh   = blockIdx.y;
    const int b    = bh >> 3;
    const int h    = bh & 7;
    const int qrow0 = b * LQ + blockIdx.x * 128;

    // zero V region (incl. j-pad) and K pad rows 77..79
    for (int i = tid; i < (AT_SMEM - AV) / 4; i += 256)
        ((uint32_t*)(sm + AV))[i] = 0;
    if (tid < 96) {
        const int rr = tid >> 5, c = tid & 31;
        *(uint32_t*)(sm + AK + (77 + rr) * 128 + c * 4) = 0;
    }

    // Q: 128 rows x 8 16B-chunks
#pragma unroll
    for (int i = 0; i < 4; ++i) {
        const int idx = i * 256 + tid;
        const int r = idx >> 3, c = idx & 7;
        cp_async16(base + AQ + swz128((uint32_t)(r * 128 + c * 16)),
                   Q + (size_t)(qrow0 + r) * 512 + h * 64 + c * 8);
    }
    // K: 77 rows x 8 chunks
#pragma unroll
    for (int i = 0; i < 3; ++i) {
        const int idx = i * 256 + tid;
        if (idx < 616) {
            const int j = idx >> 3, c = idx & 7;
            cp_async16(base + AK + swz128((uint32_t)(j * 128 + c * 16)),
                       KV + (size_t)(b * LK + j) * 1024 + h * 64 + c * 8);
        }
    }
    CP_COMMIT();

    // scalar transpose V -> VT [d][j]
    for (int idx = tid; idx < LK * 64; idx += 256) {
        const int j = idx >> 6, d = idx & 63;
        const __half v = KV[(size_t)(b * LK + j) * 1024 + 512 + h * 64 + d];
        *(__half*)(sm + AV + d * VT_B + j * 2) = v;
    }
    CP_WAIT0();
    __syncthreads();

    // ---- S = Q K^T, 10 n8 tiles ----
    float s[10][4];
#pragma unroll
    for (int nt = 0; nt < 10; ++nt)
#pragma unroll
        for (int q = 0; q < 4; ++q) s[nt][q] = 0.f;

    const uint32_t aBase = (uint32_t)((w * 16 + (lane & 15)) * 128 + (lane >> 4) * 16);
    const uint32_t bRowK = (uint32_t)(((lane & 7)) * 128 + ((lane >> 3) & 1) * 16);
#pragma unroll
    for (int kb = 0; kb < 4; ++kb) {
        const uint32_t ao = aBase + kb * 32;
        uint32_t qf[4];
        ldmatrix_x4(qf, base + AQ + (ao ^ ((ao >> 3) & 0x70)));
#pragma unroll
        for (int nt = 0; nt < 10; ++nt) {
            const uint32_t bo = bRowK + nt * 8 * 128 + kb * 32;
            uint32_t kf[2];
            ldmatrix_x2(kf, base + AK + (bo ^ ((bo >> 3) & 0x70)));
            mma16816h(s[nt], qf, kf);
        }
    }

    // mask j >= 77 (tile nt=9)
    const int t = lane & 3;
    if (t == 2) { s[9][1] = -1e30f; s[9][3] = -1e30f; }
    if (t == 3) { s[9][0] = -1e30f; s[9][1] = -1e30f; s[9][2] = -1e30f; s[9][3] = -1e30f; }

    // ---- softmax on fragments ----
    float mlo = -1e30f, mhi = -1e30f;
#pragma unroll
    for (int nt = 0; nt < 10; ++nt) {
        mlo = fmaxf(mlo, fmaxf(s[nt][0], s[nt][1]));
        mhi = fmaxf(mhi, fmaxf(s[nt][2], s[nt][3]));
    }
#pragma unroll
    for (int o = 1; o <= 2; o <<= 1) {
        mlo = fmaxf(mlo, __shfl_xor_sync(0xffffffffu, mlo, o));
        mhi = fmaxf(mhi, __shfl_xor_sync(0xffffffffu, mhi, o));
    }
    float slo = 0.f, shi = 0.f;
#pragma unroll
    for (int nt = 0; nt < 10; ++nt) {
        s[nt][0] = __expf(s[nt][0] - mlo);
        s[nt][1] = __expf(s[nt][1] - mlo);
        s[nt][2] = __expf(s[nt][2] - mhi);
        s[nt][3] = __expf(s[nt][3] - mhi);
        slo += s[nt][0] + s[nt][1];
        shi += s[nt][2] + s[nt][3];
    }
#pragma unroll
    for (int o = 1; o <= 2; o <<= 1) {
        slo += __shfl_xor_sync(0xffffffffu, slo, o);
        shi += __shfl_xor_sync(0xffffffffu, shi, o);
    }
    const float rlo = 1.f / slo, rhi = 1.f / shi;

    // ---- O = P V ----
    float o[8][4];
#pragma unroll
    for (int dn = 0; dn < 8; ++dn)
#pragma unroll
        for (int q = 0; q < 4; ++q) o[dn][q] = 0.f;

    const uint32_t bRowV = (uint32_t)(((lane & 7)) * VT_B + ((lane >> 3) & 1) * 16);
#pragma unroll
    for (int kt = 0; kt < 5; ++kt) {
        uint32_t p[4];
        p[0] = pack_h2(s[2 * kt][0],     s[2 * kt][1]);
        p[1] = pack_h2(s[2 * kt][2],     s[2 * kt][3]);
        p[2] = pack_h2(s[2 * kt + 1][0], s[2 * kt + 1][1]);
        p[3] = pack_h2(s[2 * kt + 1][2], s[2 * kt + 1][3]);
#pragma unroll
        for (int dn = 0; dn < 8; ++dn) {
            const uint32_t bo = bRowV + dn * 8 * VT_B + kt * 32;
            uint32_t vf[2];
            ldmatrix_x2(vf, base + AV + bo);
            mma16816h(o[dn], p, vf);
        }
    }

    const int g = lane >> 2;
    const size_t rA = (size_t)(qrow0 + w * 16 + g) * 512 + h * 64;
    const size_t rB = rA + 8 * 512;
#pragma unroll
    for (int dn = 0; dn < 8; ++dn) {
        const int col = dn * 8 + 2 * t;
        *(uint32_t*)(Oa + rA + col) = pack_h2(o[dn][0] * rlo, o[dn][1] * rlo);
        *(uint32_t*)(Oa + rB + col) = pack_h2(o[dn][2] * rhi, o[dn][3] * rhi);
    }
}

// ===========================================================================
extern "C" void kernel_launch(void* const* d_in, const int* in_sizes, int n_in,
                              void* d_out, int out_size)
{
    (void)in_sizes; (void)n_in; (void)out_size;
    const float* x    = (const float*)d_in[0];
    const float* cond = (const float*)d_in[1];
    const float* w_q  = (const float*)d_in[2];
    const float* w_k  = (const float*)d_in[3];
    const float* w_v  = (const float*)d_in[4];
    const float* w_o  = (const float*)d_in[5];
    float* out = (float*)d_out;

    __half *xh, *ch, *ah, *qh, *wqh, *woh, *wkvh, *kvh;
    cudaGetSymbolAddress((void**)&xh, g_xh);
    cudaGetSymbolAddress((void**)&ch, g_ch);
    cudaGetSymbolAddress((void**)&ah, g_ah);
    cudaGetSymbolAddress((void**)&qh, g_qh);
    cudaGetSymbolAddress((void**)&wqh, g_wqh);
    cudaGetSymbolAddress((void**)&woh, g_woh);
    cudaGetSymbolAddress((void**)&wkvh, g_wkvh);
    cudaGetSymbolAddress((void**)&kvh, g_kvh);

    cudaFuncSetAttribute((void*)gemm_n<512, 512, 1>,  cudaFuncAttributeMaxDynamicSharedMemorySize, SM_N);
    cudaFuncSetAttribute((void*)gemm_n<512, 512, 0>,  cudaFuncAttributeMaxDynamicSharedMemorySize, SM_N);
    cudaFuncSetAttribute((void*)gemm_n<768, 1024, 1>, cudaFuncAttributeMaxDynamicSharedMemorySize, SM_N);
    cudaFuncSetAttribute((void*)attn_mma, cudaFuncAttributeMaxDynamicSharedMemorySize, AT_SMEM);

    const int XN4 = B_ * LQ * DMODEL / 4;
    const int WN4 = DMODEL * INNER / 4;
    const int CN4 = MKV * DCOND / 4;
    const int WKN4 = INNER * DCOND / 4;
    cvt_h<<<(XN4 + 255) / 256, 256>>>((const float4*)x, (uint2*)xh, XN4);
    cvt_h<<<(CN4 + 255) / 256, 256>>>((const float4*)cond, (uint2*)ch, CN4);
    cvt_h<<<(WN4 + 255) / 256, 256>>>((const float4*)w_q, (uint2*)wqh, WN4);
    cvt_h<<<(WN4 + 255) / 256, 256>>>((const float4*)w_o, (uint2*)woh, WN4);
    cvt_h<<<(WKN4 + 255) / 256, 256>>>((const float4*)w_k, (uint2*)wkvh, WKN4);
    cvt_h<<<(WKN4 + 255) / 256, 256>>>((const float4*)w_v,
        (uint2*)(wkvh + (size_t)INNER * DCOND), WKN4);

    // K+V projection: single fp16 everywhere -> kvh [MKVP, 1024]
    gemm_n<768, 1024, 1><<<dim3(MKVP / 128, 16), 256, SM_N>>>(ch, wkvh, nullptr, kvh, 1.f);

    // Q projection: fp16 out pre-scaled 0.125
    gemm_n<512, 512, 1><<<dim3(512, 8), 256, SM_N>>>(xh, wqh, nullptr, qh, 0.125f);

    // fp16 tensor-core attention (Q/K/V single)
    attn_mma<<<dim3(LQ / 128, B_ * NH), 256, AT_SMEM>>>(qh, kvh, ah);

    // Output projection -> fp32
    gemm_n<512, 512, 0><<<dim3(512, 8), 256, SM_N>>>(ah, woh, out, nullptr, 1.f);
}

// round 16
// speedup vs baseline: 1.2259x; 1.2259x over previous
#include <cuda_runtime.h>
#include <cuda_fp16.h>
#include <cstdint>
#include <math.h>

#define B_     16
#define LQ     4096
#define LK     77
#define DMODEL 512
#define DCOND  768
#define NH     8
#define HD     64
#define INNER  512   // NH*HD
#define MKV    1232  // B_*LK
#define MKVP   1280  // padded to 128

// Scratch (allocation-free rule: __device__ globals; zero-initialized)
__device__ __half g_xh[(size_t)B_ * LQ * DMODEL];     // x fp16
__device__ __half g_ch[MKVP * DCOND];                 // cond fp16 (pad rows 0)
__device__ __half g_ah[(size_t)B_ * LQ * INNER];      // attention out fp16
__device__ __half g_wqh[DMODEL * INNER];              // w_q single fp16
__device__ __half g_woh[DMODEL * INNER];              // w_o single fp16
__device__ __half g_wkvh[2 * INNER * DCOND];          // [w_k ; w_v] single fp16
__device__ __half g_kvh[(size_t)MKVP * 1024];         // K cols 0..511, V 512..1023

// ===========================================================================
// Helpers (base PTX only)
// ===========================================================================
__device__ __forceinline__ uint32_t smem_u32(const void* p) {
    uint32_t a;
    asm("{ .reg .u64 t; cvta.to.shared.u64 t, %1; cvt.u32.u64 %0, t; }" : "=r"(a) : "l"(p));
    return a;
}
__device__ __forceinline__ uint32_t swz128(uint32_t off) { return off ^ ((off >> 3) & 0x70); }

__device__ __forceinline__ void ldmatrix_x4(uint32_t* r, uint32_t addr) {
    asm volatile("ldmatrix.sync.aligned.m8n8.x4.shared.b16 {%0,%1,%2,%3}, [%4];"
        : "=r"(r[0]), "=r"(r[1]), "=r"(r[2]), "=r"(r[3]) : "r"(addr));
}
__device__ __forceinline__ void ldmatrix_x2(uint32_t* r, uint32_t addr) {
    asm volatile("ldmatrix.sync.aligned.m8n8.x2.shared.b16 {%0,%1}, [%2];"
        : "=r"(r[0]), "=r"(r[1]) : "r"(addr));
}
__device__ __forceinline__ void mma16816h(float* d, const uint32_t* a, const uint32_t* b) {
    asm volatile("mma.sync.aligned.m16n8k16.row.col.f32.f16.f16.f32 "
        "{%0,%1,%2,%3}, {%4,%5,%6,%7}, {%8,%9}, {%0,%1,%2,%3};"
        : "+f"(d[0]), "+f"(d[1]), "+f"(d[2]), "+f"(d[3])
        : "r"(a[0]), "r"(a[1]), "r"(a[2]), "r"(a[3]), "r"(b[0]), "r"(b[1]));
}
__device__ __forceinline__ void cp_async16(uint32_t dst, const void* src) {
    asm volatile("cp.async.cg.shared.global [%0], [%1], 16;" :: "r"(dst), "l"(src));
}
#define CP_COMMIT() asm volatile("cp.async.commit_group;" ::: "memory")
#define CP_WAIT3()  asm volatile("cp.async.wait_group 3;" ::: "memory")
#define CP_WAIT2()  asm volatile("cp.async.wait_group 2;" ::: "memory")
#define CP_WAIT0()  asm volatile("cp.async.wait_group 0;" ::: "memory")

__device__ __forceinline__ uint32_t pack_h2(float x, float y) {
    __half2 h = __floats2half2_rn(x, y);
    return *(const uint32_t*)&h;
}

// fp32 -> single fp16
__global__ void cvt_h(const float4* __restrict__ in, uint2* __restrict__ out, int n4)
{
    const int i = blockIdx.x * blockDim.x + threadIdx.x;
    if (i >= n4) return;
    const float4 v = in[i];
    out[i] = make_uint2(pack_h2(v.x, v.y), pack_h2(v.z, v.w));
}

// ===========================================================================
// Narrow-tile fp16 GEMM (single B): 128x64 tile, K-chunk 64, 4-stage cp.async,
// 256 thr (8 warps, 4m x 2n), warp tile 32x32. 2 CTA/SM.
// OUT: 0 = fp32 C; 1 = fp16 single (premul).
// ===========================================================================
#define SM_N (4 * 24576)

template <int KDIM, int LDC, int OUT>
__global__ void __launch_bounds__(256, 2)
gemm_n(const __half* __restrict__ A, const __half* __restrict__ Bw,
       float* __restrict__ C, __half* __restrict__ Oh, float premul)
{
    constexpr int NCHUNK = KDIM / 64;
    extern __shared__ char sm[];
    const uint32_t base = smem_u32(sm);
    const int tid  = threadIdx.x;
    const int wid  = tid >> 5;
    const int lane = tid & 31;
    const int wm   = wid & 3;
    const int wn   = wid >> 2;

    const int m0 = blockIdx.x * 128;
    const int n0 = blockIdx.y * 64;
    const __half* A0 = A  + (size_t)m0 * KDIM;
    const __half* B0 = Bw + (size_t)n0 * KDIM;

    float acc[2][4][4];
#pragma unroll
    for (int mt = 0; mt < 2; ++mt)
#pragma unroll
        for (int nt = 0; nt < 4; ++nt)
#pragma unroll
            for (int q = 0; q < 4; ++q) acc[mt][nt][q] = 0.f;

    uint32_t aRow0[2], bRow0[4];
#pragma unroll
    for (int mt = 0; mt < 2; ++mt)
        aRow0[mt] = (uint32_t)((wm * 32 + mt * 16 + (lane & 15)) * 128 + (lane >> 4) * 16);
#pragma unroll
    for (int nt = 0; nt < 4; ++nt)
        bRow0[nt] = (uint32_t)((wn * 32 + nt * 8 + (lane & 7)) * 128 + ((lane >> 3) & 1) * 16);

    auto issue_chunk = [&](int c, int buf) {
        const int kc = c * 64;
        const uint32_t tb = base + buf * 24576;
#pragma unroll
        for (int i = 0; i < 4; ++i) {
            const int idx = i * 256 + tid;
            const int row = idx >> 3, c8 = idx & 7;
            cp_async16(tb + swz128((uint32_t)(row * 128 + c8 * 16)),
                       A0 + (size_t)row * KDIM + kc + c8 * 8);
        }
#pragma unroll
        for (int i = 0; i < 2; ++i) {
            const int idx = i * 256 + tid;
            const int row = idx >> 3, c8 = idx & 7;
            cp_async16(tb + 16384 + swz128((uint32_t)(row * 128 + c8 * 16)),
                       B0 + (size_t)row * KDIM + kc + c8 * 8);
        }
    };

    issue_chunk(0, 0); CP_COMMIT();
    issue_chunk(1, 1); CP_COMMIT();
    issue_chunk(2, 2); CP_COMMIT();
    issue_chunk(3, 3); CP_COMMIT();

    for (int c = 0; c < NCHUNK; ++c) {
        const int buf = c & 3;
        CP_WAIT3();
        __syncthreads();

        const uint32_t bufA = base + buf * 24576;
        const uint32_t bufB = bufA + 16384;
#pragma unroll
        for (int kb = 0; kb < 4; ++kb) {
            const uint32_t kbyte = kb * 32;
            uint32_t Af[2][4], Bf[4][2];
#pragma unroll
            for (int mt = 0; mt < 2; ++mt) {
                const uint32_t off = aRow0[mt] + kbyte;
                ldmatrix_x4(Af[mt], bufA + (off ^ ((off >> 3) & 0x70)));
            }
#pragma unroll
            for (int nt = 0; nt < 4; ++nt) {
                const uint32_t off = bRow0[nt] + kbyte;
                ldmatrix_x2(Bf[nt], bufB + (off ^ ((off >> 3) & 0x70)));
            }
#pragma unroll
            for (int mt = 0; mt < 2; ++mt)
#pragma unroll
                for (int nt = 0; nt < 4; ++nt)
                    mma16816h(acc[mt][nt], Af[mt], Bf[nt]);
        }
        __syncthreads();
        if (c + 4 < NCHUNK) issue_chunk(c + 4, buf);
        CP_COMMIT();
    }

#pragma unroll
    for (int mt = 0; mt < 2; ++mt) {
        const int r = m0 + wm * 32 + mt * 16 + (lane >> 2);
#pragma unroll
        for (int nt = 0; nt < 4; ++nt) {
            const int cc = n0 + wn * 32 + nt * 8 + (lane & 3) * 2;
            if (OUT == 0) {
                *(float2*)(C + (size_t)r * LDC + cc)       = make_float2(acc[mt][nt][0], acc[mt][nt][1]);
                *(float2*)(C + (size_t)(r + 8) * LDC + cc) = make_float2(acc[mt][nt][2], acc[mt][nt][3]);
            } else {
                *(uint32_t*)(Oh + (size_t)r * LDC + cc)       = pack_h2(acc[mt][nt][0] * premul, acc[mt][nt][1] * premul);
                *(uint32_t*)(Oh + (size_t)(r + 8) * LDC + cc) = pack_h2(acc[mt][nt][2] * premul, acc[mt][nt][3] * premul);
            }
        }
    }
}

// ===========================================================================
// FUSED Q-projection + attention. grid (B_*NH, LQ/128), 256 threads, 2 CTA/SM.
// Phase 1: Q[128,64] = x[128,512] @ wq_head[64,512]^T (3-stage cp.async GEMM),
//          fragments scaled 0.125 and stored to swizzled smem AQ.
// Phase 2: FA attention vs K/V (single fp16), as in R15.
// smem: 3x24KB GEMM stages | AQ 16KB | AK 10KB | VT 11.3KB = 111.6KB.
// ===========================================================================
#define FST     24576
#define FAQ     (3 * FST)            // 73728
#define FAK     (FAQ + 16384)        // 90112
#define FAV     (FAK + 10240)        // 100352
#define VT_B    176
#define FA_SMEM (FAV + 64 * VT_B)    // 111616

__global__ void __launch_bounds__(256, 2)
fused_qattn(const __half* __restrict__ X, const __half* __restrict__ Wq,
            const __half* __restrict__ KV, __half* __restrict__ Oa)
{
    extern __shared__ char sm[];
    const uint32_t base = smem_u32(sm);
    const int tid  = threadIdx.x;
    const int wid  = tid >> 5;
    const int lane = tid & 31;
    const int bh   = blockIdx.x;           // bh fast: heads of a batch share x in L2
    const int b    = bh >> 3;
    const int h    = bh & 7;
    const int qrow0 = b * LQ + blockIdx.y * 128;

    // zero VT region (incl. j-pad) and K pad rows 77..79
    for (int i = tid; i < (FA_SMEM - FAV) / 4; i += 256)
        ((uint32_t*)(sm + FAV))[i] = 0;
    if (tid < 96) {
        const int rr = tid >> 5, c = tid & 31;
        *(uint32_t*)(sm + FAK + (77 + rr) * 128 + c * 4) = 0;
    }

    // K: 77 rows x 8 16B-chunks (own group, completes early)
#pragma unroll
    for (int i = 0; i < 3; ++i) {
        const int idx = i * 256 + tid;
        if (idx < 616) {
            const int j = idx >> 3, c = idx & 7;
            cp_async16(base + FAK + swz128((uint32_t)(j * 128 + c * 16)),
                       KV + (size_t)(b * LK + j) * 1024 + h * 64 + c * 8);
        }
    }
    CP_COMMIT();

    // ---------------- Phase 1: Q = x @ wq_head^T ----------------
    const __half* A0 = X  + (size_t)qrow0 * 512;
    const __half* B0 = Wq + (size_t)(h * 64) * 512;
    const int wm = wid & 3;
    const int wn = wid >> 2;

    float acc[2][4][4];
#pragma unroll
    for (int mt = 0; mt < 2; ++mt)
#pragma unroll
        for (int nt = 0; nt < 4; ++nt)
#pragma unroll
            for (int q = 0; q < 4; ++q) acc[mt][nt][q] = 0.f;

    uint32_t aRow0[2], bRow0[4];
#pragma unroll
    for (int mt = 0; mt < 2; ++mt)
        aRow0[mt] = (uint32_t)((wm * 32 + mt * 16 + (lane & 15)) * 128 + (lane >> 4) * 16);
#pragma unroll
    for (int nt = 0; nt < 4; ++nt)
        bRow0[nt] = (uint32_t)((wn * 32 + nt * 8 + (lane & 7)) * 128 + ((lane >> 3) & 1) * 16);

    auto issue_chunk = [&](int c, int buf) {
        const int kc = c * 64;
        const uint32_t tb = base + buf * FST;
#pragma unroll
        for (int i = 0; i < 4; ++i) {
            const int idx = i * 256 + tid;
            const int row = idx >> 3, c8 = idx & 7;
            cp_async16(tb + swz128((uint32_t)(row * 128 + c8 * 16)),
                       A0 + (size_t)row * 512 + kc + c8 * 8);
        }
#pragma unroll
        for (int i = 0; i < 2; ++i) {
            const int idx = i * 256 + tid;
            const int row = idx >> 3, c8 = idx & 7;
            cp_async16(tb + 16384 + swz128((uint32_t)(row * 128 + c8 * 16)),
                       B0 + (size_t)row * 512 + kc + c8 * 8);
        }
    };

    issue_chunk(0, 0); CP_COMMIT();
    issue_chunk(1, 1); CP_COMMIT();
    issue_chunk(2, 2); CP_COMMIT();

    for (int c = 0; c < 8; ++c) {
        const int buf = c % 3;
        CP_WAIT2();
        __syncthreads();

        const uint32_t bufA = base + buf * FST;
        const uint32_t bufB = bufA + 16384;
#pragma unroll
        for (int kb = 0; kb < 4; ++kb) {
            const uint32_t kbyte = kb * 32;
            uint32_t Af[2][4], Bf[4][2];
#pragma unroll
            for (int mt = 0; mt < 2; ++mt) {
                const uint32_t off = aRow0[mt] + kbyte;
                ldmatrix_x4(Af[mt], bufA + (off ^ ((off >> 3) & 0x70)));
            }
#pragma unroll
            for (int nt = 0; nt < 4; ++nt) {
                const uint32_t off = bRow0[nt] + kbyte;
                ldmatrix_x2(Bf[nt], bufB + (off ^ ((off >> 3) & 0x70)));
            }
#pragma unroll
            for (int mt = 0; mt < 2; ++mt)
#pragma unroll
                for (int nt = 0; nt < 4; ++nt)
                    mma16816h(acc[mt][nt], Af[mt], Bf[nt]);
        }
        __syncthreads();
        if (c + 3 < 8) issue_chunk(c + 3, buf);
        CP_COMMIT();
    }

    // Store scaled Q fragments to swizzled AQ (4B stores share the 16B-chunk XOR)
#pragma unroll
    for (int mt = 0; mt < 2; ++mt) {
        const int r = wm * 32 + mt * 16 + (lane >> 2);
#pragma unroll
        for (int nt = 0; nt < 4; ++nt) {
            const int cb = (wn * 32 + nt * 8 + (lane & 3) * 2) * 2;   // byte col
            *(uint32_t*)(sm + FAQ + swz128((uint32_t)(r * 128 + cb))) =
                pack_h2(acc[mt][nt][0] * 0.125f, acc[mt][nt][1] * 0.125f);
            *(uint32_t*)(sm + FAQ + swz128((uint32_t)((r + 8) * 128 + cb))) =
                pack_h2(acc[mt][nt][2] * 0.125f, acc[mt][nt][3] * 0.125f);
        }
    }

    // scalar transpose V -> VT [d][j]
    for (int idx = tid; idx < LK * 64; idx += 256) {
        const int j = idx >> 6, d = idx & 63;
        const __half v = KV[(size_t)(b * LK + j) * 1024 + 512 + h * 64 + d];
        *(__half*)(sm + FAV + d * VT_B + j * 2) = v;
    }
    CP_WAIT0();
    __syncthreads();

    // ---------------- Phase 2: attention ----------------
    const int w = wid;
    float s[10][4];
#pragma unroll
    for (int nt = 0; nt < 10; ++nt)
#pragma unroll
        for (int q = 0; q < 4; ++q) s[nt][q] = 0.f;

    const uint32_t aBase = (uint32_t)((w * 16 + (lane & 15)) * 128 + (lane >> 4) * 16);
    const uint32_t bRowK = (uint32_t)(((lane & 7)) * 128 + ((lane >> 3) & 1) * 16);
#pragma unroll
    for (int kb = 0; kb < 4; ++kb) {
        const uint32_t ao = aBase + kb * 32;
        uint32_t qf[4];
        ldmatrix_x4(qf, base + FAQ + (ao ^ ((ao >> 3) & 0x70)));
#pragma unroll
        for (int nt = 0; nt < 10; ++nt) {
            const uint32_t bo = bRowK + nt * 8 * 128 + kb * 32;
            uint32_t kf[2];
            ldmatrix_x2(kf, base + FAK + (bo ^ ((bo >> 3) & 0x70)));
            mma16816h(s[nt], qf, kf);
        }
    }

    const int t = lane & 3;
    if (t == 2) { s[9][1] = -1e30f; s[9][3] = -1e30f; }
    if (t == 3) { s[9][0] = -1e30f; s[9][1] = -1e30f; s[9][2] = -1e30f; s[9][3] = -1e30f; }

    float mlo = -1e30f, mhi = -1e30f;
#pragma unroll
    for (int nt = 0; nt < 10; ++nt) {
        mlo = fmaxf(mlo, fmaxf(s[nt][0], s[nt][1]));
        mhi = fmaxf(mhi, fmaxf(s[nt][2], s[nt][3]));
    }
#pragma unroll
    for (int o = 1; o <= 2; o <<= 1) {
        mlo = fmaxf(mlo, __shfl_xor_sync(0xffffffffu, mlo, o));
        mhi = fmaxf(mhi, __shfl_xor_sync(0xffffffffu, mhi, o));
    }
    float slo = 0.f, shi = 0.f;
#pragma unroll
    for (int nt = 0; nt < 10; ++nt) {
        s[nt][0] = __expf(s[nt][0] - mlo);
        s[nt][1] = __expf(s[nt][1] - mlo);
        s[nt][2] = __expf(s[nt][2] - mhi);
        s[nt][3] = __expf(s[nt][3] - mhi);
        slo += s[nt][0] + s[nt][1];
        shi += s[nt][2] + s[nt][3];
    }
#pragma unroll
    for (int o = 1; o <= 2; o <<= 1) {
        slo += __shfl_xor_sync(0xffffffffu, slo, o);
        shi += __shfl_xor_sync(0xffffffffu, shi, o);
    }
    const float rlo = 1.f / slo, rhi = 1.f / shi;

    float o[8][4];
#pragma unroll
    for (int dn = 0; dn < 8; ++dn)
#pragma unroll
        for (int q = 0; q < 4; ++q) o[dn][q] = 0.f;

    const uint32_t bRowV = (uint32_t)(((lane & 7)) * VT_B + ((lane >> 3) & 1) * 16);
#pragma unroll
    for (int kt = 0; kt < 5; ++kt) {
        uint32_t p[4];
        p[0] = pack_h2(s[2 * kt][0],     s[2 * kt][1]);
        p[1] = pack_h2(s[2 * kt][2],     s[2 * kt][3]);
        p[2] = pack_h2(s[2 * kt + 1][0], s[2 * kt + 1][1]);
        p[3] = pack_h2(s[2 * kt + 1][2], s[2 * kt + 1][3]);
#pragma unroll
        for (int dn = 0; dn < 8; ++dn) {
            const uint32_t bo = bRowV + dn * 8 * VT_B + kt * 32;
            uint32_t vf[2];
            ldmatrix_x2(vf, base + FAV + bo);
            mma16816h(o[dn], p, vf);
        }
    }

    const int g = lane >> 2;
    const size_t rA = (size_t)(qrow0 + w * 16 + g) * 512 + h * 64;
    const size_t rB = rA + 8 * 512;
#pragma unroll
    for (int dn = 0; dn < 8; ++dn) {
        const int col = dn * 8 + 2 * t;
        *(uint32_t*)(Oa + rA + col) = pack_h2(o[dn][0] * rlo, o[dn][1] * rlo);
        *(uint32_t*)(Oa + rB + col) = pack_h2(o[dn][2] * rhi, o[dn][3] * rhi);
    }
}

// ===========================================================================
extern "C" void kernel_launch(void* const* d_in, const int* in_sizes, int n_in,
                              void* d_out, int out_size)
{
    (void)in_sizes; (void)n_in; (void)out_size;
    const float* x    = (const float*)d_in[0];
    const float* cond = (const float*)d_in[1];
    const float* w_q  = (const float*)d_in[2];
    const float* w_k  = (const float*)d_in[3];
    const float* w_v  = (const float*)d_in[4];
    const float* w_o  = (const float*)d_in[5];
    float* out = (float*)d_out;

    __half *xh, *ch, *ah, *wqh, *woh, *wkvh, *kvh;
    cudaGetSymbolAddress((void**)&xh, g_xh);
    cudaGetSymbolAddress((void**)&ch, g_ch);
    cudaGetSymbolAddress((void**)&ah, g_ah);
    cudaGetSymbolAddress((void**)&wqh, g_wqh);
    cudaGetSymbolAddress((void**)&woh, g_woh);
    cudaGetSymbolAddress((void**)&wkvh, g_wkvh);
    cudaGetSymbolAddress((void**)&kvh, g_kvh);

    cudaFuncSetAttribute((void*)gemm_n<512, 512, 0>,  cudaFuncAttributeMaxDynamicSharedMemorySize, SM_N);
    cudaFuncSetAttribute((void*)gemm_n<768, 1024, 1>, cudaFuncAttributeMaxDynamicSharedMemorySize, SM_N);
    cudaFuncSetAttribute((void*)fused_qattn, cudaFuncAttributeMaxDynamicSharedMemorySize, FA_SMEM);

    const int XN4 = B_ * LQ * DMODEL / 4;
    const int WN4 = DMODEL * INNER / 4;
    const int CN4 = MKV * DCOND / 4;
    const int WKN4 = INNER * DCOND / 4;
    cvt_h<<<(XN4 + 255) / 256, 256>>>((const float4*)x, (uint2*)xh, XN4);
    cvt_h<<<(CN4 + 255) / 256, 256>>>((const float4*)cond, (uint2*)ch, CN4);
    cvt_h<<<(WN4 + 255) / 256, 256>>>((const float4*)w_q, (uint2*)wqh, WN4);
    cvt_h<<<(WN4 + 255) / 256, 256>>>((const float4*)w_o, (uint2*)woh, WN4);
    cvt_h<<<(WKN4 + 255) / 256, 256>>>((const float4*)w_k, (uint2*)wkvh, WKN4);
    cvt_h<<<(WKN4 + 255) / 256, 256>>>((const float4*)w_v,
        (uint2*)(wkvh + (size_t)INNER * DCOND), WKN4);

    // K+V projection: single fp16 -> kvh [MKVP, 1024]
    gemm_n<768, 1024, 1><<<dim3(MKVP / 128, 16), 256, SM_N>>>(ch, wkvh, nullptr, kvh, 1.f);

    // Fused Q-projection + attention
    fused_qattn<<<dim3(B_ * NH, LQ / 128), 256, FA_SMEM>>>(xh, wqh, kvh, ah);

    // Output projection -> fp32
    gemm_n<512, 512, 0><<<dim3(512, 8), 256, SM_N>>>(ah, woh, out, nullptr, 1.f);
}

// round 17
// speedup vs baseline: 1.2752x; 1.0403x over previous
#include <cuda_runtime.h>
#include <cuda_fp16.h>
#include <cstdint>
#include <math.h>

#define B_     16
#define LQ     4096
#define LK     77
#define DMODEL 512
#define DCOND  768
#define NH     8
#define HD     64
#define INNER  512   // NH*HD
#define MKV    1232  // B_*LK
#define MKVP   1280  // padded to 128

// Scratch (allocation-free rule: __device__ globals; zero-initialized)
__device__ __half g_xh[(size_t)B_ * LQ * DMODEL];     // x fp16
__device__ __half g_ch[MKVP * DCOND];                 // cond fp16 (pad rows 0)
__device__ __half g_ah[(size_t)B_ * LQ * INNER];      // attention out fp16
__device__ __half g_wqh[DMODEL * INNER];              // w_q * 0.125 fp16
__device__ __half g_woh[DMODEL * INNER];              // w_o fp16
__device__ __half g_wkvh[2 * INNER * DCOND];          // [w_k ; w_v] fp16
__device__ __half g_kvh[(size_t)MKVP * 1024];         // K cols 0..511, V 512..1023

// ===========================================================================
// Helpers (base PTX only)
// ===========================================================================
__device__ __forceinline__ uint32_t smem_u32(const void* p) {
    uint32_t a;
    asm("{ .reg .u64 t; cvta.to.shared.u64 t, %1; cvt.u32.u64 %0, t; }" : "=r"(a) : "l"(p));
    return a;
}
__device__ __forceinline__ uint32_t swz128(uint32_t off) { return off ^ ((off >> 3) & 0x70); }

__device__ __forceinline__ void ldmatrix_x4(uint32_t* r, uint32_t addr) {
    asm volatile("ldmatrix.sync.aligned.m8n8.x4.shared.b16 {%0,%1,%2,%3}, [%4];"
        : "=r"(r[0]), "=r"(r[1]), "=r"(r[2]), "=r"(r[3]) : "r"(addr));
}
__device__ __forceinline__ void ldmatrix_x2(uint32_t* r, uint32_t addr) {
    asm volatile("ldmatrix.sync.aligned.m8n8.x2.shared.b16 {%0,%1}, [%2];"
        : "=r"(r[0]), "=r"(r[1]) : "r"(addr));
}
__device__ __forceinline__ void mma16816h(float* d, const uint32_t* a, const uint32_t* b) {
    asm volatile("mma.sync.aligned.m16n8k16.row.col.f32.f16.f16.f32 "
        "{%0,%1,%2,%3}, {%4,%5,%6,%7}, {%8,%9}, {%0,%1,%2,%3};"
        : "+f"(d[0]), "+f"(d[1]), "+f"(d[2]), "+f"(d[3])
        : "r"(a[0]), "r"(a[1]), "r"(a[2]), "r"(a[3]), "r"(b[0]), "r"(b[1]));
}
__device__ __forceinline__ void cp_async16(uint32_t dst, const void* src) {
    asm volatile("cp.async.cg.shared.global [%0], [%1], 16;" :: "r"(dst), "l"(src));
}
#define CP_COMMIT() asm volatile("cp.async.commit_group;" ::: "memory")
#define CP_WAIT3()  asm volatile("cp.async.wait_group 3;" ::: "memory")
#define CP_WAIT2()  asm volatile("cp.async.wait_group 2;" ::: "memory")
#define CP_WAIT0()  asm volatile("cp.async.wait_group 0;" ::: "memory")

__device__ __forceinline__ uint32_t pack_h2(float x, float y) {
    __half2 h = __floats2half2_rn(x, y);
    return *(const uint32_t*)&h;
}

// fp32 -> fp16 (xSCALE), 2 independent float4 per thread for MLP
__global__ void cvt_h(const float4* __restrict__ in, uint2* __restrict__ out,
                      int n4, float scale)
{
    const int i = (blockIdx.x * blockDim.x + threadIdx.x) * 2;
    if (i >= n4) return;
    const float4 v0 = in[i];
    const float4 v1 = in[i + 1];
    out[i]     = make_uint2(pack_h2(v0.x * scale, v0.y * scale),
                            pack_h2(v0.z * scale, v0.w * scale));
    out[i + 1] = make_uint2(pack_h2(v1.x * scale, v1.y * scale),
                            pack_h2(v1.z * scale, v1.w * scale));
}

// ===========================================================================
// Narrow-tile fp16 GEMM (single B): 128x64 tile, K-chunk 64, NSTAGE cp.async
// stages, 256 thr (8 warps, 4m x 2n), warp tile 32x32, OCC CTAs/SM.
// OUT: 0 = fp32 C; 1 = fp16 single (premul).
// ===========================================================================
template <int KDIM, int LDC, int OUT, int NSTAGE, int OCC>
__global__ void __launch_bounds__(256, OCC)
gemm_n(const __half* __restrict__ A, const __half* __restrict__ Bw,
       float* __restrict__ C, __half* __restrict__ Oh, float premul)
{
    constexpr int NCHUNK = KDIM / 64;
    extern __shared__ char sm[];
    const uint32_t base = smem_u32(sm);
    const int tid  = threadIdx.x;
    const int wid  = tid >> 5;
    const int lane = tid & 31;
    const int wm   = wid & 3;
    const int wn   = wid >> 2;

    const int m0 = blockIdx.x * 128;
    const int n0 = blockIdx.y * 64;
    const __half* A0 = A  + (size_t)m0 * KDIM;
    const __half* B0 = Bw + (size_t)n0 * KDIM;

    float acc[2][4][4];
#pragma unroll
    for (int mt = 0; mt < 2; ++mt)
#pragma unroll
        for (int nt = 0; nt < 4; ++nt)
#pragma unroll
            for (int q = 0; q < 4; ++q) acc[mt][nt][q] = 0.f;

    uint32_t aRow0[2], bRow0[4];
#pragma unroll
    for (int mt = 0; mt < 2; ++mt)
        aRow0[mt] = (uint32_t)((wm * 32 + mt * 16 + (lane & 15)) * 128 + (lane >> 4) * 16);
#pragma unroll
    for (int nt = 0; nt < 4; ++nt)
        bRow0[nt] = (uint32_t)((wn * 32 + nt * 8 + (lane & 7)) * 128 + ((lane >> 3) & 1) * 16);

    auto issue_chunk = [&](int c, int buf) {
        const int kc = c * 64;
        const uint32_t tb = base + buf * 24576;
#pragma unroll
        for (int i = 0; i < 4; ++i) {
            const int idx = i * 256 + tid;
            const int row = idx >> 3, c8 = idx & 7;
            cp_async16(tb + swz128((uint32_t)(row * 128 + c8 * 16)),
                       A0 + (size_t)row * KDIM + kc + c8 * 8);
        }
#pragma unroll
        for (int i = 0; i < 2; ++i) {
            const int idx = i * 256 + tid;
            const int row = idx >> 3, c8 = idx & 7;
            cp_async16(tb + 16384 + swz128((uint32_t)(row * 128 + c8 * 16)),
                       B0 + (size_t)row * KDIM + kc + c8 * 8);
        }
    };

#pragma unroll
    for (int s = 0; s < NSTAGE; ++s) { issue_chunk(s, s); CP_COMMIT(); }

    for (int c = 0; c < NCHUNK; ++c) {
        const int buf = c % NSTAGE;
        if (NSTAGE == 4) CP_WAIT3(); else CP_WAIT2();
        __syncthreads();

        const uint32_t bufA = base + buf * 24576;
        const uint32_t bufB = bufA + 16384;
#pragma unroll
        for (int kb = 0; kb < 4; ++kb) {
            const uint32_t kbyte = kb * 32;
            uint32_t Af[2][4], Bf[4][2];
#pragma unroll
            for (int mt = 0; mt < 2; ++mt) {
                const uint32_t off = aRow0[mt] + kbyte;
                ldmatrix_x4(Af[mt], bufA + (off ^ ((off >> 3) & 0x70)));
            }
#pragma unroll
            for (int nt = 0; nt < 4; ++nt) {
                const uint32_t off = bRow0[nt] + kbyte;
                ldmatrix_x2(Bf[nt], bufB + (off ^ ((off >> 3) & 0x70)));
            }
#pragma unroll
            for (int mt = 0; mt < 2; ++mt)
#pragma unroll
                for (int nt = 0; nt < 4; ++nt)
                    mma16816h(acc[mt][nt], Af[mt], Bf[nt]);
        }
        __syncthreads();
        if (c + NSTAGE < NCHUNK) issue_chunk(c + NSTAGE, buf);
        CP_COMMIT();
    }

#pragma unroll
    for (int mt = 0; mt < 2; ++mt) {
        const int r = m0 + wm * 32 + mt * 16 + (lane >> 2);
#pragma unroll
        for (int nt = 0; nt < 4; ++nt) {
            const int cc = n0 + wn * 32 + nt * 8 + (lane & 3) * 2;
            if (OUT == 0) {
                *(float2*)(C + (size_t)r * LDC + cc)       = make_float2(acc[mt][nt][0], acc[mt][nt][1]);
                *(float2*)(C + (size_t)(r + 8) * LDC + cc) = make_float2(acc[mt][nt][2], acc[mt][nt][3]);
            } else {
                *(uint32_t*)(Oh + (size_t)r * LDC + cc)       = pack_h2(acc[mt][nt][0] * premul, acc[mt][nt][1] * premul);
                *(uint32_t*)(Oh + (size_t)(r + 8) * LDC + cc) = pack_h2(acc[mt][nt][2] * premul, acc[mt][nt][3] * premul);
            }
        }
    }
}

// ===========================================================================
// FUSED Q-projection + attention. grid (B_*NH, LQ/128), 256 threads, 2 CTA/SM.
// (w_q pre-scaled by 0.125 at conversion time.)
// ===========================================================================
#define FST     24576
#define FAQ     (3 * FST)
#define FAK     (FAQ + 16384)
#define FAV     (FAK + 10240)
#define VT_B    176
#define FA_SMEM (FAV + 64 * VT_B)

__global__ void __launch_bounds__(256, 2)
fused_qattn(const __half* __restrict__ X, const __half* __restrict__ Wq,
            const __half* __restrict__ KV, __half* __restrict__ Oa)
{
    extern __shared__ char sm[];
    const uint32_t base = smem_u32(sm);
    const int tid  = threadIdx.x;
    const int wid  = tid >> 5;
    const int lane = tid & 31;
    const int bh   = blockIdx.x;
    const int b    = bh >> 3;
    const int h    = bh & 7;
    const int qrow0 = b * LQ + blockIdx.y * 128;

    for (int i = tid; i < (FA_SMEM - FAV) / 4; i += 256)
        ((uint32_t*)(sm + FAV))[i] = 0;
    if (tid < 96) {
        const int rr = tid >> 5, c = tid & 31;
        *(uint32_t*)(sm + FAK + (77 + rr) * 128 + c * 4) = 0;
    }

#pragma unroll
    for (int i = 0; i < 3; ++i) {
        const int idx = i * 256 + tid;
        if (idx < 616) {
            const int j = idx >> 3, c = idx & 7;
            cp_async16(base + FAK + swz128((uint32_t)(j * 128 + c * 16)),
                       KV + (size_t)(b * LK + j) * 1024 + h * 64 + c * 8);
        }
    }
    CP_COMMIT();

    // ---------------- Phase 1: Q = x @ wq_head^T (wq pre-scaled) ----------
    const __half* A0 = X  + (size_t)qrow0 * 512;
    const __half* B0 = Wq + (size_t)(h * 64) * 512;
    const int wm = wid & 3;
    const int wn = wid >> 2;

    float acc[2][4][4];
#pragma unroll
    for (int mt = 0; mt < 2; ++mt)
#pragma unroll
        for (int nt = 0; nt < 4; ++nt)
#pragma unroll
            for (int q = 0; q < 4; ++q) acc[mt][nt][q] = 0.f;

    uint32_t aRow0[2], bRow0[4];
#pragma unroll
    for (int mt = 0; mt < 2; ++mt)
        aRow0[mt] = (uint32_t)((wm * 32 + mt * 16 + (lane & 15)) * 128 + (lane >> 4) * 16);
#pragma unroll
    for (int nt = 0; nt < 4; ++nt)
        bRow0[nt] = (uint32_t)((wn * 32 + nt * 8 + (lane & 7)) * 128 + ((lane >> 3) & 1) * 16);

    auto issue_chunk = [&](int c, int buf) {
        const int kc = c * 64;
        const uint32_t tb = base + buf * FST;
#pragma unroll
        for (int i = 0; i < 4; ++i) {
            const int idx = i * 256 + tid;
            const int row = idx >> 3, c8 = idx & 7;
            cp_async16(tb + swz128((uint32_t)(row * 128 + c8 * 16)),
                       A0 + (size_t)row * 512 + kc + c8 * 8);
        }
#pragma unroll
        for (int i = 0; i < 2; ++i) {
            const int idx = i * 256 + tid;
            const int row = idx >> 3, c8 = idx & 7;
            cp_async16(tb + 16384 + swz128((uint32_t)(row * 128 + c8 * 16)),
                       B0 + (size_t)row * 512 + kc + c8 * 8);
        }
    };

    issue_chunk(0, 0); CP_COMMIT();
    issue_chunk(1, 1); CP_COMMIT();
    issue_chunk(2, 2); CP_COMMIT();

    for (int c = 0; c < 8; ++c) {
        const int buf = c % 3;
        CP_WAIT2();
        __syncthreads();

        const uint32_t bufA = base + buf * FST;
        const uint32_t bufB = bufA + 16384;
#pragma unroll
        for (int kb = 0; kb < 4; ++kb) {
            const uint32_t kbyte = kb * 32;
            uint32_t Af[2][4], Bf[4][2];
#pragma unroll
            for (int mt = 0; mt < 2; ++mt) {
                const uint32_t off = aRow0[mt] + kbyte;
                ldmatrix_x4(Af[mt], bufA + (off ^ ((off >> 3) & 0x70)));
            }
#pragma unroll
            for (int nt = 0; nt < 4; ++nt) {
                const uint32_t off = bRow0[nt] + kbyte;
                ldmatrix_x2(Bf[nt], bufB + (off ^ ((off >> 3) & 0x70)));
            }
#pragma unroll
            for (int mt = 0; mt < 2; ++mt)
#pragma unroll
                for (int nt = 0; nt < 4; ++nt)
                    mma16816h(acc[mt][nt], Af[mt], Bf[nt]);
        }
        __syncthreads();
        if (c + 3 < 8) issue_chunk(c + 3, buf);
        CP_COMMIT();
    }

    // Store Q fragments to swizzled AQ
#pragma unroll
    for (int mt = 0; mt < 2; ++mt) {
        const int r = wm * 32 + mt * 16 + (lane >> 2);
#pragma unroll
        for (int nt = 0; nt < 4; ++nt) {
            const int cb = (wn * 32 + nt * 8 + (lane & 3) * 2) * 2;
            *(uint32_t*)(sm + FAQ + swz128((uint32_t)(r * 128 + cb))) =
                pack_h2(acc[mt][nt][0], acc[mt][nt][1]);
            *(uint32_t*)(sm + FAQ + swz128((uint32_t)((r + 8) * 128 + cb))) =
                pack_h2(acc[mt][nt][2], acc[mt][nt][3]);
        }
    }

    // scalar transpose V -> VT [d][j]
    for (int idx = tid; idx < LK * 64; idx += 256) {
        const int j = idx >> 6, d = idx & 63;
        const __half v = KV[(size_t)(b * LK + j) * 1024 + 512 + h * 64 + d];
        *(__half*)(sm + FAV + d * VT_B + j * 2) = v;
    }
    CP_WAIT0();
    __syncthreads();

    // ---------------- Phase 2: attention ----------------
    const int w = wid;
    float s[10][4];
#pragma unroll
    for (int nt = 0; nt < 10; ++nt)
#pragma unroll
        for (int q = 0; q < 4; ++q) s[nt][q] = 0.f;

    const uint32_t aBase = (uint32_t)((w * 16 + (lane & 15)) * 128 + (lane >> 4) * 16);
    const uint32_t bRowK = (uint32_t)(((lane & 7)) * 128 + ((lane >> 3) & 1) * 16);
#pragma unroll
    for (int kb = 0; kb < 4; ++kb) {
        const uint32_t ao = aBase + kb * 32;
        uint32_t qf[4];
        ldmatrix_x4(qf, base + FAQ + (ao ^ ((ao >> 3) & 0x70)));
#pragma unroll
        for (int nt = 0; nt < 10; ++nt) {
            const uint32_t bo = bRowK + nt * 8 * 128 + kb * 32;
            uint32_t kf[2];
            ldmatrix_x2(kf, base + FAK + (bo ^ ((bo >> 3) & 0x70)));
            mma16816h(s[nt], qf, kf);
        }
    }

    const int t = lane & 3;
    if (t == 2) { s[9][1] = -1e30f; s[9][3] = -1e30f; }
    if (t == 3) { s[9][0] = -1e30f; s[9][1] = -1e30f; s[9][2] = -1e30f; s[9][3] = -1e30f; }

    float mlo = -1e30f, mhi = -1e30f;
#pragma unroll
    for (int nt = 0; nt < 10; ++nt) {
        mlo = fmaxf(mlo, fmaxf(s[nt][0], s[nt][1]));
        mhi = fmaxf(mhi, fmaxf(s[nt][2], s[nt][3]));
    }
#pragma unroll
    for (int o = 1; o <= 2; o <<= 1) {
        mlo = fmaxf(mlo, __shfl_xor_sync(0xffffffffu, mlo, o));
        mhi = fmaxf(mhi, __shfl_xor_sync(0xffffffffu, mhi, o));
    }
    float slo = 0.f, shi = 0.f;
#pragma unroll
    for (int nt = 0; nt < 10; ++nt) {
        s[nt][0] = __expf(s[nt][0] - mlo);
        s[nt][1] = __expf(s[nt][1] - mlo);
        s[nt][2] = __expf(s[nt][2] - mhi);
        s[nt][3] = __expf(s[nt][3] - mhi);
        slo += s[nt][0] + s[nt][1];
        shi += s[nt][2] + s[nt][3];
    }
#pragma unroll
    for (int o = 1; o <= 2; o <<= 1) {
        slo += __shfl_xor_sync(0xffffffffu, slo, o);
        shi += __shfl_xor_sync(0xffffffffu, shi, o);
    }
    const float rlo = 1.f / slo, rhi = 1.f / shi;

    float o[8][4];
#pragma unroll
    for (int dn = 0; dn < 8; ++dn)
#pragma unroll
        for (int q = 0; q < 4; ++q) o[dn][q] = 0.f;

    const uint32_t bRowV = (uint32_t)(((lane & 7)) * VT_B + ((lane >> 3) & 1) * 16);
#pragma unroll
    for (int kt = 0; kt < 5; ++kt) {
        uint32_t p[4];
        p[0] = pack_h2(s[2 * kt][0],     s[2 * kt][1]);
        p[1] = pack_h2(s[2 * kt][2],     s[2 * kt][3]);
        p[2] = pack_h2(s[2 * kt + 1][0], s[2 * kt + 1][1]);
        p[3] = pack_h2(s[2 * kt + 1][2], s[2 * kt + 1][3]);
#pragma unroll
        for (int dn = 0; dn < 8; ++dn) {
            const uint32_t bo = bRowV + dn * 8 * VT_B + kt * 32;
            uint32_t vf[2];
            ldmatrix_x2(vf, base + FAV + bo);
            mma16816h(o[dn], p, vf);
        }
    }

    const int g = lane >> 2;
    const size_t rA = (size_t)(qrow0 + w * 16 + g) * 512 + h * 64;
    const size_t rB = rA + 8 * 512;
#pragma unroll
    for (int dn = 0; dn < 8; ++dn) {
        const int col = dn * 8 + 2 * t;
        *(uint32_t*)(Oa + rA + col) = pack_h2(o[dn][0] * rlo, o[dn][1] * rlo);
        *(uint32_t*)(Oa + rB + col) = pack_h2(o[dn][2] * rhi, o[dn][3] * rhi);
    }
}

// ===========================================================================
extern "C" void kernel_launch(void* const* d_in, const int* in_sizes, int n_in,
                              void* d_out, int out_size)
{
    (void)in_sizes; (void)n_in; (void)out_size;
    const float* x    = (const float*)d_in[0];
    const float* cond = (const float*)d_in[1];
    const float* w_q  = (const float*)d_in[2];
    const float* w_k  = (const float*)d_in[3];
    const float* w_v  = (const float*)d_in[4];
    const float* w_o  = (const float*)d_in[5];
    float* out = (float*)d_out;

    __half *xh, *ch, *ah, *wqh, *woh, *wkvh, *kvh;
    cudaGetSymbolAddress((void**)&xh, g_xh);
    cudaGetSymbolAddress((void**)&ch, g_ch);
    cudaGetSymbolAddress((void**)&ah, g_ah);
    cudaGetSymbolAddress((void**)&wqh, g_wqh);
    cudaGetSymbolAddress((void**)&woh, g_woh);
    cudaGetSymbolAddress((void**)&wkvh, g_wkvh);
    cudaGetSymbolAddress((void**)&kvh, g_kvh);

    cudaFuncSetAttribute((void*)gemm_n<512, 512, 0, 3, 3>,  cudaFuncAttributeMaxDynamicSharedMemorySize, 3 * 24576);
    cudaFuncSetAttribute((void*)gemm_n<768, 1024, 1, 3, 3>, cudaFuncAttributeMaxDynamicSharedMemorySize, 3 * 24576);
    cudaFuncSetAttribute((void*)fused_qattn, cudaFuncAttributeMaxDynamicSharedMemorySize, FA_SMEM);

    const int XN4 = B_ * LQ * DMODEL / 4;
    const int WN4 = DMODEL * INNER / 4;
    const int CN4 = MKV * DCOND / 4;
    const int WKN4 = INNER * DCOND / 4;
    cvt_h<<<(XN4 / 2 + 255) / 256, 256>>>((const float4*)x, (uint2*)xh, XN4, 1.f);
    cvt_h<<<(CN4 / 2 + 255) / 256, 256>>>((const float4*)cond, (uint2*)ch, CN4, 1.f);
    cvt_h<<<(WN4 / 2 + 255) / 256, 256>>>((const float4*)w_q, (uint2*)wqh, WN4, 0.125f);
    cvt_h<<<(WN4 / 2 + 255) / 256, 256>>>((const float4*)w_o, (uint2*)woh, WN4, 1.f);
    cvt_h<<<(WKN4 / 2 + 255) / 256, 256>>>((const float4*)w_k, (uint2*)wkvh, WKN4, 1.f);
    cvt_h<<<(WKN4 / 2 + 255) / 256, 256>>>((const float4*)w_v,
        (uint2*)(wkvh + (size_t)INNER * DCOND), WKN4, 1.f);

    // K+V projection -> kvh [MKVP, 1024], 3 CTA/SM
    gemm_n<768, 1024, 1, 3, 3><<<dim3(MKVP / 128, 16), 256, 3 * 24576>>>(
        ch, wkvh, nullptr, kvh, 1.f);

    // Fused Q-projection + attention (wq pre-scaled)
    fused_qattn<<<dim3(B_ * NH, LQ / 128), 256, FA_SMEM>>>(xh, wqh, kvh, ah);

    // Output projection -> fp32, 3 CTA/SM
    gemm_n<512, 512, 0, 3, 3><<<dim3(512, 8), 256, 3 * 24576>>>(
        ah, woh, out, nullptr, 1.f);
}